// round 7
// baseline (speedup 1.0000x reference)
#include <cuda_runtime.h>
#include <cuda_bf16.h>
#include <cstdint>
#include <cstddef>

#define N_NODES 8192
#define DHID 64

// ---------------- scratch (device globals; no allocation allowed) ----------------
__device__ __align__(16) __nv_bfloat16 g_HclT[DHID * N_NODES];  // H_cl^T bf16 [64][8192]
__device__ __align__(16) __nv_bfloat16 g_HueT[DHID * N_NODES];  // H_ue^T bf16 [64][8192]
__device__ __align__(16) float g_Xc1[N_NODES * DHID];
__device__ __align__(16) float g_Xc2[N_NODES * DHID];
__device__ __align__(16) float g_Xue[N_NODES * DHID];
__device__ __align__(16) float g_part[512 * DHID];

__device__ __forceinline__ float relu_(float x) { return fmaxf(x, 0.0f); }

__device__ __forceinline__ uint32_t smem_u32(const void* p) {
    uint32_t a;
    asm("{ .reg .u64 t; cvta.to.shared.u64 t, %1; cvt.u32.u64 %0, t; }" : "=r"(a) : "l"(p));
    return a;
}

__device__ __forceinline__ void ldsm_x4(uint32_t* r, uint32_t addr) {
    asm volatile("ldmatrix.sync.aligned.m8n8.x4.shared.b16 {%0,%1,%2,%3}, [%4];"
                 : "=r"(r[0]), "=r"(r[1]), "=r"(r[2]), "=r"(r[3]) : "r"(addr));
}

__device__ __forceinline__ void mma_bf16(float* c, const uint32_t* a, const uint32_t* b) {
    asm volatile(
        "mma.sync.aligned.m16n8k16.row.col.f32.bf16.bf16.f32 "
        "{%0,%1,%2,%3}, {%4,%5,%6,%7}, {%8,%9}, {%0,%1,%2,%3};"
        : "+f"(c[0]), "+f"(c[1]), "+f"(c[2]), "+f"(c[3])
        : "r"(a[0]), "r"(a[1]), "r"(a[2]), "r"(a[3]), "r"(b[0]), "r"(b[1]));
}

__device__ __forceinline__ uint32_t pack_bf16x2(float2 v) {
    __nv_bfloat162 b = __float22bfloat162_rn(v);
    return *(uint32_t*)&b;
}

#define CP_ASYNC16(smem, gptr) \
    asm volatile("cp.async.cg.shared.global [%0], [%1], 16;" :: "r"(smem), "l"(gptr))
#define CP_COMMIT() asm volatile("cp.async.commit_group;")
#define CP_WAIT2()  asm volatile("cp.async.wait_group 2;")

// ---------------- GEMM body: C[8192, ND] = A(fp32) @ Ht^T (Ht bf16 [n][k]) ----------------
// NT=1: ND=64,  C0 = g_Xc1 (Bt0 = HclT)
// NT=2: ND=128, cols 0-63 -> C0 = g_Xc2 (Bt0 = HueT), cols 64-127 -> C1 = g_Xue (Bt1 = HclT)
template <int NT>
__device__ __forceinline__ void gemm_body(const float* __restrict__ A,
                                          const __nv_bfloat16* __restrict__ Bt0,
                                          const __nv_bfloat16* __restrict__ Bt1,
                                          float* __restrict__ C0, float* __restrict__ C1,
                                          int m0, char* smem) {
    constexpr int ND     = 64 * NT;
    constexpr int KC     = 32;                 // k per chunk
    constexpr int NCH    = N_NODES / KC;       // 256 chunks
    constexpr int STAGES = 4;
    constexpr int ASTR   = 160;                // fp32 A row stride (128B data + 32 pad)
    constexpr int ABUF   = 128 * ASTR;         // 20480 B per stage
    constexpr int BSTR   = 80;                 // bf16 B row stride
    constexpr int BBUF   = 128 * BSTR;         // 10240 B per stage (sized for NT=2)
    constexpr int NP     = ND / 32;            // B ldmatrix-x4 pairs per warp

    const int tid  = threadIdx.x;
    const int lane = tid & 31;
    const int wid  = tid >> 5;
    const int wm   = wid & 3;                  // 4 M-warps x 32 rows
    const int wn   = wid >> 2;                 // 2 N-warps x ND/2 cols
    const int g    = lane >> 2;
    const int t    = lane & 3;

    const uint32_t sbu   = smem_u32(smem);
    const uint32_t sA0   = sbu;                       // 4 stages of A
    const uint32_t sB0   = sbu + STAGES * ABUF;       // 4 stages of B

    // ---- cp.async slot maps ----
    // A: 128 rows x 8 x 16B slots = 1024 slots, 4 per thread
    const float* gAp[4];
    uint32_t aoffS[4];
    #pragma unroll
    for (int i = 0; i < 4; ++i) {
        int slot = tid + i * 256;
        int row = slot >> 3, seg = slot & 7;
        gAp[i]   = A + (size_t)(m0 + row) * N_NODES + seg * 4;
        aoffS[i] = (uint32_t)(row * ASTR + seg * 16);
    }
    // B: ND rows x 4 x 16B slots, NT per thread
    const __nv_bfloat16* gBp[NT];
    uint32_t boffS[NT];
    #pragma unroll
    for (int j = 0; j < NT; ++j) {
        int slot = tid + j * 256;
        int row = slot >> 2, seg = slot & 3;
        const __nv_bfloat16* base = (NT == 2 && row >= 64)
            ? (Bt1 + (size_t)(row - 64) * N_NODES) : (Bt0 + (size_t)row * N_NODES);
        gBp[j]   = base + seg * 8;
        boffS[j] = (uint32_t)(row * BSTR + seg * 16);
    }

    auto ISSUE = [&](int kt) {
        const int s = kt & (STAGES - 1);
        const uint32_t sa = sA0 + s * ABUF;
        #pragma unroll
        for (int i = 0; i < 4; ++i)
            CP_ASYNC16(sa + aoffS[i], gAp[i] + (size_t)kt * KC);
        const uint32_t sb = sB0 + s * BBUF;
        #pragma unroll
        for (int j = 0; j < NT; ++j)
            CP_ASYNC16(sb + boffS[j], gBp[j] + (size_t)kt * KC);
    };

    // ---- B ldmatrix lane offsets (validated layout, 80B stride) ----
    uint32_t boffL[NP][2];
    #pragma unroll
    for (int np = 0; np < NP; ++np)
        #pragma unroll
        for (int ks = 0; ks < 2; ++ks)
            boffL[np][ks] = (uint32_t)((wn * (ND / 2) + np * 16 + (lane >> 4) * 8 + (lane & 7)) * BSTR +
                                       (ks * 16 + ((lane >> 3) & 1) * 8) * 2);

    // ---- A fragment base (fp32 smem, LDS.64 + cvt path) ----
    const int afrag_base = (wm * 32 + g) * ASTR + t * 8;

    float acc[2][2 * NP][4];
    #pragma unroll
    for (int mt = 0; mt < 2; ++mt)
        #pragma unroll
        for (int nt = 0; nt < 2 * NP; ++nt)
            #pragma unroll
            for (int i = 0; i < 4; ++i) acc[mt][nt][i] = 0.0f;

    // ---- prologue: fill STAGES-1 stages ----
    #pragma unroll
    for (int s = 0; s < STAGES - 1; ++s) { ISSUE(s); CP_COMMIT(); }

    for (int kt = 0; kt < NCH; ++kt) {
        const int st = kt & (STAGES - 1);
        CP_WAIT2();
        __syncthreads();

        // issue chunk kt+3 into stage (kt+3)%4 (whose data was consumed at iter kt-1)
        if (kt + STAGES - 1 < NCH) ISSUE(kt + STAGES - 1);
        CP_COMMIT();

        const char*    Ab = smem + st * ABUF + afrag_base;
        const uint32_t Bb = sB0 + st * BBUF;

        #pragma unroll
        for (int ks = 0; ks < 2; ++ks) {
            uint32_t af[2][4], bf[2 * NP][2];
            #pragma unroll
            for (int mt = 0; mt < 2; ++mt) {
                const char* p = Ab + mt * 16 * ASTR + ks * 64;
                af[mt][0] = pack_bf16x2(*(const float2*)(p));
                af[mt][1] = pack_bf16x2(*(const float2*)(p + 8 * ASTR));
                af[mt][2] = pack_bf16x2(*(const float2*)(p + 32));
                af[mt][3] = pack_bf16x2(*(const float2*)(p + 8 * ASTR + 32));
            }
            #pragma unroll
            for (int np = 0; np < NP; ++np) {
                uint32_t tt[4];
                ldsm_x4(tt, Bb + boffL[np][ks]);
                bf[np * 2][0] = tt[0]; bf[np * 2][1] = tt[1];
                bf[np * 2 + 1][0] = tt[2]; bf[np * 2 + 1][1] = tt[3];
            }
            #pragma unroll
            for (int mt = 0; mt < 2; ++mt)
                #pragma unroll
                for (int nt = 0; nt < 2 * NP; ++nt)
                    mma_bf16(acc[mt][nt], af[mt], bf[nt]);
        }
    }

    // ---- epilogue ----
    const int tig = lane & 3;
    #pragma unroll
    for (int mt = 0; mt < 2; ++mt) {
        int row = m0 + wm * 32 + mt * 16 + g;
        #pragma unroll
        for (int nt = 0; nt < 2 * NP; ++nt) {
            int col = wn * (ND / 2) + nt * 8 + tig * 2;
            float* Cg = C0;
            int cc = col;
            if (NT == 2 && col >= 64) { Cg = C1; cc = col - 64; }
            *(float2*)(Cg + (size_t)row * 64 + cc)       = make_float2(acc[mt][nt][0], acc[mt][nt][1]);
            *(float2*)(Cg + (size_t)(row + 8) * 64 + cc) = make_float2(acc[mt][nt][2], acc[mt][nt][3]);
        }
    }
}

__global__ void __launch_bounds__(256)
gnn_gemm_kernel(const float* __restrict__ Acl, const float* __restrict__ Aue) {
    extern __shared__ __align__(128) char smem[];   // 4*20480 + 4*10240 = 122880 B
    const int b = blockIdx.x;
    if (b < 64) gemm_body<1>(Acl, g_HclT, nullptr, g_Xc1, nullptr, b * 128, smem);
    else        gemm_body<2>(Aue, g_HueT, g_HclT, g_Xc2, g_Xue, (b - 64) * 128, smem);
}

// ---------------- layer 0 H (in_dim = 2), writes H^T bf16 ----------------
__global__ void h0_kernel(const float* __restrict__ X1, const float* __restrict__ X2,
                          const float* __restrict__ XU,
                          const float* __restrict__ w1, const float* __restrict__ b1,
                          const float* __restrict__ w2, const float* __restrict__ b2,
                          const float* __restrict__ w3, const float* __restrict__ b3) {
    const int r = blockIdx.x * 256 + threadIdx.x;
    const float2 x1 = *(const float2*)(X1 + r * 2);
    const float2 x2 = *(const float2*)(X2 + r * 2);
    const float2 xu = *(const float2*)(XU + r * 2);
    #pragma unroll 8
    for (int c = 0; c < 64; ++c) {
        float h1 = relu_(fmaf(x1.x, __ldg(w1 + c), fmaf(x1.y, __ldg(w1 + 64 + c), __ldg(b1 + c))));
        float h2 = relu_(fmaf(x2.x, __ldg(w2 + c), fmaf(x2.y, __ldg(w2 + 64 + c), __ldg(b2 + c))));
        float h3 = relu_(fmaf(xu.x, __ldg(w3 + c), fmaf(xu.y, __ldg(w3 + 64 + c), __ldg(b3 + c))));
        g_HclT[c * N_NODES + r] = __float2bfloat16(h1 + h2);
        g_HueT[c * N_NODES + r] = __float2bfloat16(h3);
    }
}

// ---------------- layers 1..2 H (in_dim = 64), writes H^T bf16 ----------------
__global__ void __launch_bounds__(256) h_layer_kernel(const float* __restrict__ w1,
                                                      const float* __restrict__ b1,
                                                      const float* __restrict__ w2,
                                                      const float* __restrict__ b2,
                                                      const float* __restrict__ w3,
                                                      const float* __restrict__ b3) {
    __shared__ float xs1[16][64], xs2[16][64], xs3[16][64];
    __shared__ __align__(16) __nv_bfloat16 hs_cl[64][16];
    __shared__ __align__(16) __nv_bfloat16 hs_ue[64][16];
    const int tid = threadIdx.x;
    const int r0  = blockIdx.x * 16;
    #pragma unroll
    for (int i = 0; i < 4; ++i) {
        int idx = tid + i * 256;
        int r = idx >> 6, k = idx & 63;
        xs1[r][k] = g_Xc1[(size_t)(r0 + r) * 64 + k];
        xs2[r][k] = g_Xc2[(size_t)(r0 + r) * 64 + k];
        xs3[r][k] = g_Xue[(size_t)(r0 + r) * 64 + k];
    }
    __syncthreads();
    const int c  = tid & 63;
    const int rg = tid >> 6;
    float a1[4] = {0, 0, 0, 0}, a2[4] = {0, 0, 0, 0}, a3[4] = {0, 0, 0, 0};
    #pragma unroll 8
    for (int k = 0; k < 64; ++k) {
        float w1k = w1[k * 64 + c], w2k = w2[k * 64 + c], w3k = w3[k * 64 + c];
        #pragma unroll
        for (int i = 0; i < 4; ++i) {
            int r = rg + i * 4;
            a1[i] = fmaf(xs1[r][k], w1k, a1[i]);
            a2[i] = fmaf(xs2[r][k], w2k, a2[i]);
            a3[i] = fmaf(xs3[r][k], w3k, a3[i]);
        }
    }
    const float bb1 = b1[c], bb2 = b2[c], bb3 = b3[c];
    #pragma unroll
    for (int i = 0; i < 4; ++i) {
        int r = rg + i * 4;
        hs_cl[c][r] = __float2bfloat16(relu_(a1[i] + bb1) + relu_(a2[i] + bb2));
        hs_ue[c][r] = __float2bfloat16(relu_(a3[i] + bb3));
    }
    __syncthreads();
    if (tid < 128) {
        int cc = tid >> 1, hf = tid & 1;
        *(uint4*)(g_HclT + cc * N_NODES + r0 + hf * 8) = *(const uint4*)(&hs_cl[cc][hf * 8]);
    } else {
        int tt = tid - 128;
        int cc = tt >> 1, hf = tt & 1;
        *(uint4*)(g_HueT + cc * N_NODES + r0 + hf * 8) = *(const uint4*)(&hs_ue[cc][hf * 8]);
    }
}

// ---------------- layer 3: H_cl + column-sum partials (X updates are dead) ----------------
__global__ void __launch_bounds__(256) h_pool_kernel(const float* __restrict__ w1,
                                                     const float* __restrict__ b1,
                                                     const float* __restrict__ w2,
                                                     const float* __restrict__ b2) {
    __shared__ float xs1[16][64], xs2[16][64];
    __shared__ float red[4][64];
    const int tid = threadIdx.x;
    const int r0  = blockIdx.x * 16;
    #pragma unroll
    for (int i = 0; i < 4; ++i) {
        int idx = tid + i * 256;
        int r = idx >> 6, k = idx & 63;
        xs1[r][k] = g_Xc1[(size_t)(r0 + r) * 64 + k];
        xs2[r][k] = g_Xc2[(size_t)(r0 + r) * 64 + k];
    }
    __syncthreads();
    const int c  = tid & 63;
    const int rg = tid >> 6;
    float a1[4] = {0, 0, 0, 0}, a2[4] = {0, 0, 0, 0};
    #pragma unroll 8
    for (int k = 0; k < 64; ++k) {
        float w1k = w1[k * 64 + c], w2k = w2[k * 64 + c];
        #pragma unroll
        for (int i = 0; i < 4; ++i) {
            int r = rg + i * 4;
            a1[i] = fmaf(xs1[r][k], w1k, a1[i]);
            a2[i] = fmaf(xs2[r][k], w2k, a2[i]);
        }
    }
    const float bb1 = b1[c], bb2 = b2[c];
    float s = 0.0f;
    #pragma unroll
    for (int i = 0; i < 4; ++i) s += relu_(a1[i] + bb1) + relu_(a2[i] + bb2);
    red[rg][c] = s;
    __syncthreads();
    if (tid < 64)
        g_part[blockIdx.x * 64 + tid] = red[0][tid] + red[1][tid] + red[2][tid] + red[3][tid];
}

// ---------------- final: reduce partials + 2-layer MLP -> out[0] ----------------
__global__ void final_kernel(const float* __restrict__ Qw1, const float* __restrict__ Qb1,
                             const float* __restrict__ Qw2, const float* __restrict__ Qb2,
                             float* __restrict__ out) {
    __shared__ float red[4][64];
    __shared__ float pooled[64];
    __shared__ float z[64];
    int tid = threadIdx.x;
    int c = tid & 63, g = tid >> 6;
    float s = 0.0f;
    for (int p = g; p < 512; p += 4) s += g_part[p * 64 + c];
    red[g][c] = s;
    __syncthreads();
    if (tid < 64) pooled[tid] = red[0][tid] + red[1][tid] + red[2][tid] + red[3][tid];
    __syncthreads();
    if (tid < 64) {
        float a = Qb1[tid];
        #pragma unroll 8
        for (int i = 0; i < 64; ++i) a = fmaf(pooled[i], Qw1[i * 64 + tid], a);
        z[tid] = relu_(a);
    }
    __syncthreads();
    if (tid == 0) {
        float s2 = Qb2[0];
        for (int j = 0; j < 64; ++j) s2 = fmaf(z[j], Qw2[j], s2);
        out[0] = s2;
    }
}

// ---------------- launch ----------------
extern "C" void kernel_launch(void* const* d_in, const int* in_sizes, int n_in,
                              void* d_out, int out_size) {
    (void)in_sizes; (void)n_in; (void)out_size;
    const float* X1   = (const float*)d_in[0];
    const float* X2   = (const float*)d_in[1];
    const float* XU   = (const float*)d_in[2];
    const float* Acl  = (const float*)d_in[3];
    const float* Aue  = (const float*)d_in[4];
    const float* W1w0 = (const float*)d_in[5];
    const float* W1b0 = (const float*)d_in[6];
    const float* W1w  = (const float*)d_in[7];
    const float* W1b  = (const float*)d_in[8];
    const float* W2w0 = (const float*)d_in[9];
    const float* W2b0 = (const float*)d_in[10];
    const float* W2w  = (const float*)d_in[11];
    const float* W2b  = (const float*)d_in[12];
    const float* W3w0 = (const float*)d_in[13];
    const float* W3b0 = (const float*)d_in[14];
    const float* W3w  = (const float*)d_in[15];
    const float* W3b  = (const float*)d_in[16];
    const float* Qw1  = (const float*)d_in[17];
    const float* Qb1  = (const float*)d_in[18];
    const float* Qw2  = (const float*)d_in[19];
    const float* Qb2  = (const float*)d_in[20];
    float* out = (float*)d_out;

    const int DSMEM = 4 * 20480 + 4 * 10240;  // 122880 B
    cudaFuncSetAttribute(gnn_gemm_kernel, cudaFuncAttributeMaxDynamicSharedMemorySize, DSMEM);

    // layer 0
    h0_kernel<<<32, 256>>>(X1, X2, XU, W1w0, W1b0, W2w0, W2b0, W3w0, W3b0);
    gnn_gemm_kernel<<<128, 256, DSMEM>>>(Acl, Aue);

    // layers 1..2
    for (int l = 1; l <= 2; ++l) {
        h_layer_kernel<<<512, 256>>>(W1w + (l - 1) * 4096, W1b + (l - 1) * 64,
                                     W2w + (l - 1) * 4096, W2b + (l - 1) * 64,
                                     W3w + (l - 1) * 4096, W3b + (l - 1) * 64);
        gnn_gemm_kernel<<<128, 256, DSMEM>>>(Acl, Aue);
    }

    // layer 3: H_cl only + pooling partials, then final MLP
    h_pool_kernel<<<512, 256>>>(W1w + 2 * 4096, W1b + 2 * 64, W2w + 2 * 4096, W2b + 2 * 64);
    final_kernel<<<1, 256>>>(Qw1, Qb1, Qw2, Qb2, out);
}

// round 9
// speedup vs baseline: 1.3769x; 1.3769x over previous
#include <cuda_runtime.h>
#include <cuda_bf16.h>
#include <cstdint>
#include <cstddef>

#define N_NODES 8192
#define DHID 64

// ---------------- scratch (device globals; no allocation allowed) ----------------
__device__ __align__(16) __nv_bfloat16 g_HclT[DHID * N_NODES];  // H_cl^T bf16 [64][8192]
__device__ __align__(16) __nv_bfloat16 g_HueT[DHID * N_NODES];  // H_ue^T bf16 [64][8192]
__device__ __align__(16) float g_Xc1[N_NODES * DHID];
__device__ __align__(16) float g_Xc2[N_NODES * DHID];
__device__ __align__(16) float g_Xue[N_NODES * DHID];
__device__ __align__(16) float g_part[512 * DHID];

__device__ __forceinline__ float relu_(float x) { return fmaxf(x, 0.0f); }

__device__ __forceinline__ uint32_t smem_u32(const void* p) {
    uint32_t a;
    asm("{ .reg .u64 t; cvta.to.shared.u64 t, %1; cvt.u32.u64 %0, t; }" : "=r"(a) : "l"(p));
    return a;
}

__device__ __forceinline__ void ldsm_x4(uint32_t* r, uint32_t addr) {
    asm volatile("ldmatrix.sync.aligned.m8n8.x4.shared.b16 {%0,%1,%2,%3}, [%4];"
                 : "=r"(r[0]), "=r"(r[1]), "=r"(r[2]), "=r"(r[3]) : "r"(addr));
}

__device__ __forceinline__ void mma_bf16(float* c, const uint32_t* a, const uint32_t* b) {
    asm volatile(
        "mma.sync.aligned.m16n8k16.row.col.f32.bf16.bf16.f32 "
        "{%0,%1,%2,%3}, {%4,%5,%6,%7}, {%8,%9}, {%0,%1,%2,%3};"
        : "+f"(c[0]), "+f"(c[1]), "+f"(c[2]), "+f"(c[3])
        : "r"(a[0]), "r"(a[1]), "r"(a[2]), "r"(a[3]), "r"(b[0]), "r"(b[1]));
}

__device__ __forceinline__ uint32_t pack_bf16x2(float2 v) {
    __nv_bfloat162 b = __float22bfloat162_rn(v);
    return *(uint32_t*)&b;
}

#define CP_ASYNC16(smem, gptr) \
    asm volatile("cp.async.cg.shared.global [%0], [%1], 16;" :: "r"(smem), "l"(gptr))
#define CP_COMMIT() asm volatile("cp.async.commit_group;")
#define CP_WAIT2()  asm volatile("cp.async.wait_group 2;")

// ---------------- GEMM body: C[64-row tile, ND] = A(fp32) @ Ht^T (Ht bf16 [n][k]) ----------------
// NT=1: ND=64,  C0 = g_Xc1 (Bt0 = HclT)
// NT=2: ND=128, cols 0-63 -> C0 = g_Xc2 (Bt0 = HueT), cols 64-127 -> C1 = g_Xue (Bt1 = HclT)
template <int NT>
__device__ __forceinline__ void gemm_body(const float* __restrict__ A,
                                          const __nv_bfloat16* __restrict__ Bt0,
                                          const __nv_bfloat16* __restrict__ Bt1,
                                          float* __restrict__ C0, float* __restrict__ C1,
                                          int m0, char* smem) {
    constexpr int ND     = 64 * NT;
    constexpr int KC     = 32;                 // k per chunk
    constexpr int NCH    = N_NODES / KC;       // 256 chunks
    constexpr int STAGES = 4;
    constexpr int ASTR   = 160;                // fp32 A row stride (128B data + 32 pad)
    constexpr int ABUF   = 64 * ASTR;          // 10240 B per stage (64-row M tile)
    constexpr int BSTR   = 80;                 // bf16 B row stride
    constexpr int BBUF   = 128 * BSTR;         // 10240 B per stage (sized for NT=2)
    constexpr int NWID   = ND / 4;             // warp n-width (4 N-warps)
    constexpr int NP     = NT;                 // ldmatrix-x4 per ks per warp

    const int tid  = threadIdx.x;
    const int lane = tid & 31;
    const int wid  = tid >> 5;
    const int wm   = wid & 1;                  // 2 M-warps x 32 rows
    const int wn   = wid >> 1;                 // 4 N-warps x NWID cols
    const int g    = lane >> 2;
    const int t    = lane & 3;

    const uint32_t sbu = smem_u32(smem);
    const uint32_t sA0 = sbu;                  // STAGES stages of A
    const uint32_t sB0 = sbu + STAGES * ABUF;  // STAGES stages of B

    // ---- cp.async slot maps ----
    // A: 64 rows x 8 x 16B slots = 512 slots, 2 per thread
    const float* gAp[2];
    uint32_t aoffS[2];
    #pragma unroll
    for (int i = 0; i < 2; ++i) {
        int slot = tid + i * 256;
        int row = slot >> 3, seg = slot & 7;
        gAp[i]   = A + (size_t)(m0 + row) * N_NODES + seg * 4;
        aoffS[i] = (uint32_t)(row * ASTR + seg * 16);
    }
    // B: ND rows x 4 x 16B slots, NT per thread
    const __nv_bfloat16* gBp[NT];
    uint32_t boffS[NT];
    #pragma unroll
    for (int j = 0; j < NT; ++j) {
        int slot = tid + j * 256;
        int row = slot >> 2, seg = slot & 3;
        const __nv_bfloat16* base = (NT == 2 && row >= 64)
            ? (Bt1 + (size_t)(row - 64) * N_NODES) : (Bt0 + (size_t)row * N_NODES);
        gBp[j]   = base + seg * 8;
        boffS[j] = (uint32_t)(row * BSTR + seg * 16);
    }

    auto ISSUE = [&](int kt) {
        const int s = kt & (STAGES - 1);
        const uint32_t sa = sA0 + s * ABUF;
        #pragma unroll
        for (int i = 0; i < 2; ++i)
            CP_ASYNC16(sa + aoffS[i], gAp[i] + (size_t)kt * KC);
        const uint32_t sb = sB0 + s * BBUF;
        #pragma unroll
        for (int j = 0; j < NT; ++j)
            CP_ASYNC16(sb + boffS[j], gBp[j] + (size_t)kt * KC);
    };

    // ---- B ldmatrix lane offsets (validated layout, 80B stride) ----
    uint32_t boffL[NP][2];
    #pragma unroll
    for (int np = 0; np < NP; ++np)
        #pragma unroll
        for (int ks = 0; ks < 2; ++ks)
            boffL[np][ks] = (uint32_t)((wn * NWID + np * 16 + (lane >> 4) * 8 + (lane & 7)) * BSTR +
                                       (ks * 16 + ((lane >> 3) & 1) * 8) * 2);

    // ---- A fragment base (fp32 smem, LDS.64 + cvt path) ----
    const int afrag_base = (wm * 32 + g) * ASTR + t * 8;

    float acc[2][2 * NP][4];
    #pragma unroll
    for (int mt = 0; mt < 2; ++mt)
        #pragma unroll
        for (int nt = 0; nt < 2 * NP; ++nt)
            #pragma unroll
            for (int i = 0; i < 4; ++i) acc[mt][nt][i] = 0.0f;

    // ---- prologue: fill STAGES-1 stages ----
    #pragma unroll
    for (int s = 0; s < STAGES - 1; ++s) { ISSUE(s); CP_COMMIT(); }

    for (int kt = 0; kt < NCH; ++kt) {
        const int st = kt & (STAGES - 1);
        CP_WAIT2();
        __syncthreads();

        if (kt + STAGES - 1 < NCH) ISSUE(kt + STAGES - 1);
        CP_COMMIT();

        const char*    Ab = smem + st * ABUF + afrag_base;
        const uint32_t Bb = sB0 + st * BBUF;

        #pragma unroll
        for (int ks = 0; ks < 2; ++ks) {
            uint32_t af[2][4], bf[2 * NP][2];
            #pragma unroll
            for (int mt = 0; mt < 2; ++mt) {
                const char* p = Ab + mt * 16 * ASTR + ks * 64;
                af[mt][0] = pack_bf16x2(*(const float2*)(p));
                af[mt][1] = pack_bf16x2(*(const float2*)(p + 8 * ASTR));
                af[mt][2] = pack_bf16x2(*(const float2*)(p + 32));
                af[mt][3] = pack_bf16x2(*(const float2*)(p + 8 * ASTR + 32));
            }
            #pragma unroll
            for (int np = 0; np < NP; ++np) {
                uint32_t tt[4];
                ldsm_x4(tt, Bb + boffL[np][ks]);
                bf[np * 2][0] = tt[0]; bf[np * 2][1] = tt[1];
                bf[np * 2 + 1][0] = tt[2]; bf[np * 2 + 1][1] = tt[3];
            }
            #pragma unroll
            for (int mt = 0; mt < 2; ++mt)
                #pragma unroll
                for (int nt = 0; nt < 2 * NP; ++nt)
                    mma_bf16(acc[mt][nt], af[mt], bf[nt]);
        }
    }

    // ---- epilogue ----
    const int tig = lane & 3;
    #pragma unroll
    for (int mt = 0; mt < 2; ++mt) {
        int row = m0 + wm * 32 + mt * 16 + g;
        #pragma unroll
        for (int nt = 0; nt < 2 * NP; ++nt) {
            int col = wn * NWID + nt * 8 + tig * 2;
            float* Cg = C0;
            int cc = col;
            if (NT == 2 && col >= 64) { Cg = C1; cc = col - 64; }
            *(float2*)(Cg + (size_t)row * 64 + cc)       = make_float2(acc[mt][nt][0], acc[mt][nt][1]);
            *(float2*)(Cg + (size_t)(row + 8) * 64 + cc) = make_float2(acc[mt][nt][2], acc[mt][nt][3]);
        }
    }
}

__global__ void __launch_bounds__(256, 2)
gnn_gemm_kernel(const float* __restrict__ Acl, const float* __restrict__ Aue) {
    extern __shared__ __align__(128) char smem[];   // 4*10240 + 4*10240 = 81920 B
    const int b = blockIdx.x;
    const int tile = b >> 1;
    if ((b & 1) == 0) gemm_body<1>(Acl, g_HclT, nullptr, g_Xc1, nullptr, tile * 64, smem);
    else              gemm_body<2>(Aue, g_HueT, g_HclT, g_Xc2, g_Xue, tile * 64, smem);
}

// ---------------- layer 0 H (in_dim = 2), writes H^T bf16 ----------------
__global__ void h0_kernel(const float* __restrict__ X1, const float* __restrict__ X2,
                          const float* __restrict__ XU,
                          const float* __restrict__ w1, const float* __restrict__ b1,
                          const float* __restrict__ w2, const float* __restrict__ b2,
                          const float* __restrict__ w3, const float* __restrict__ b3) {
    const int r = blockIdx.x * 256 + threadIdx.x;
    const float2 x1 = *(const float2*)(X1 + r * 2);
    const float2 x2 = *(const float2*)(X2 + r * 2);
    const float2 xu = *(const float2*)(XU + r * 2);
    #pragma unroll 8
    for (int c = 0; c < 64; ++c) {
        float h1 = relu_(fmaf(x1.x, __ldg(w1 + c), fmaf(x1.y, __ldg(w1 + 64 + c), __ldg(b1 + c))));
        float h2 = relu_(fmaf(x2.x, __ldg(w2 + c), fmaf(x2.y, __ldg(w2 + 64 + c), __ldg(b2 + c))));
        float h3 = relu_(fmaf(xu.x, __ldg(w3 + c), fmaf(xu.y, __ldg(w3 + 64 + c), __ldg(b3 + c))));
        g_HclT[c * N_NODES + r] = __float2bfloat16(h1 + h2);
        g_HueT[c * N_NODES + r] = __float2bfloat16(h3);
    }
}

// ---------------- layers 1..2 H (in_dim = 64), writes H^T bf16 ----------------
__global__ void __launch_bounds__(256) h_layer_kernel(const float* __restrict__ w1,
                                                      const float* __restrict__ b1,
                                                      const float* __restrict__ w2,
                                                      const float* __restrict__ b2,
                                                      const float* __restrict__ w3,
                                                      const float* __restrict__ b3) {
    __shared__ float xs1[16][64], xs2[16][64], xs3[16][64];
    __shared__ __align__(16) __nv_bfloat16 hs_cl[64][16];
    __shared__ __align__(16) __nv_bfloat16 hs_ue[64][16];
    const int tid = threadIdx.x;
    const int r0  = blockIdx.x * 16;
    #pragma unroll
    for (int i = 0; i < 4; ++i) {
        int idx = tid + i * 256;
        int r = idx >> 6, k = idx & 63;
        xs1[r][k] = g_Xc1[(size_t)(r0 + r) * 64 + k];
        xs2[r][k] = g_Xc2[(size_t)(r0 + r) * 64 + k];
        xs3[r][k] = g_Xue[(size_t)(r0 + r) * 64 + k];
    }
    __syncthreads();
    const int c  = tid & 63;
    const int rg = tid >> 6;
    float a1[4] = {0, 0, 0, 0}, a2[4] = {0, 0, 0, 0}, a3[4] = {0, 0, 0, 0};
    #pragma unroll 8
    for (int k = 0; k < 64; ++k) {
        float w1k = w1[k * 64 + c], w2k = w2[k * 64 + c], w3k = w3[k * 64 + c];
        #pragma unroll
        for (int i = 0; i < 4; ++i) {
            int r = rg + i * 4;
            a1[i] = fmaf(xs1[r][k], w1k, a1[i]);
            a2[i] = fmaf(xs2[r][k], w2k, a2[i]);
            a3[i] = fmaf(xs3[r][k], w3k, a3[i]);
        }
    }
    const float bb1 = b1[c], bb2 = b2[c], bb3 = b3[c];
    #pragma unroll
    for (int i = 0; i < 4; ++i) {
        int r = rg + i * 4;
        hs_cl[c][r] = __float2bfloat16(relu_(a1[i] + bb1) + relu_(a2[i] + bb2));
        hs_ue[c][r] = __float2bfloat16(relu_(a3[i] + bb3));
    }
    __syncthreads();
    if (tid < 128) {
        int cc = tid >> 1, hf = tid & 1;
        *(uint4*)(g_HclT + cc * N_NODES + r0 + hf * 8) = *(const uint4*)(&hs_cl[cc][hf * 8]);
    } else {
        int tt = tid - 128;
        int cc = tt >> 1, hf = tt & 1;
        *(uint4*)(g_HueT + cc * N_NODES + r0 + hf * 8) = *(const uint4*)(&hs_ue[cc][hf * 8]);
    }
}

// ---------------- layer 3: H_cl + column-sum partials (X updates are dead) ----------------
__global__ void __launch_bounds__(256) h_pool_kernel(const float* __restrict__ w1,
                                                     const float* __restrict__ b1,
                                                     const float* __restrict__ w2,
                                                     const float* __restrict__ b2) {
    __shared__ float xs1[16][64], xs2[16][64];
    __shared__ float red[4][64];
    const int tid = threadIdx.x;
    const int r0  = blockIdx.x * 16;
    #pragma unroll
    for (int i = 0; i < 4; ++i) {
        int idx = tid + i * 256;
        int r = idx >> 6, k = idx & 63;
        xs1[r][k] = g_Xc1[(size_t)(r0 + r) * 64 + k];
        xs2[r][k] = g_Xc2[(size_t)(r0 + r) * 64 + k];
    }
    __syncthreads();
    const int c  = tid & 63;
    const int rg = tid >> 6;
    float a1[4] = {0, 0, 0, 0}, a2[4] = {0, 0, 0, 0};
    #pragma unroll 8
    for (int k = 0; k < 64; ++k) {
        float w1k = w1[k * 64 + c], w2k = w2[k * 64 + c];
        #pragma unroll
        for (int i = 0; i < 4; ++i) {
            int r = rg + i * 4;
            a1[i] = fmaf(xs1[r][k], w1k, a1[i]);
            a2[i] = fmaf(xs2[r][k], w2k, a2[i]);
        }
    }
    const float bb1 = b1[c], bb2 = b2[c];
    float s = 0.0f;
    #pragma unroll
    for (int i = 0; i < 4; ++i) s += relu_(a1[i] + bb1) + relu_(a2[i] + bb2);
    red[rg][c] = s;
    __syncthreads();
    if (tid < 64)
        g_part[blockIdx.x * 64 + tid] = red[0][tid] + red[1][tid] + red[2][tid] + red[3][tid];
}

// ---------------- final: reduce partials + 2-layer MLP -> out[0] ----------------
__global__ void final_kernel(const float* __restrict__ Qw1, const float* __restrict__ Qb1,
                             const float* __restrict__ Qw2, const float* __restrict__ Qb2,
                             float* __restrict__ out) {
    __shared__ float red[4][64];
    __shared__ float pooled[64];
    __shared__ float z[64];
    int tid = threadIdx.x;
    int c = tid & 63, g = tid >> 6;
    float s = 0.0f;
    for (int p = g; p < 512; p += 4) s += g_part[p * 64 + c];
    red[g][c] = s;
    __syncthreads();
    if (tid < 64) pooled[tid] = red[0][tid] + red[1][tid] + red[2][tid] + red[3][tid];
    __syncthreads();
    if (tid < 64) {
        float a = Qb1[tid];
        #pragma unroll 8
        for (int i = 0; i < 64; ++i) a = fmaf(pooled[i], Qw1[i * 64 + tid], a);
        z[tid] = relu_(a);
    }
    __syncthreads();
    if (tid == 0) {
        float s2 = Qb2[0];
        for (int j = 0; j < 64; ++j) s2 = fmaf(z[j], Qw2[j], s2);
        out[0] = s2;
    }
}

// ---------------- launch ----------------
extern "C" void kernel_launch(void* const* d_in, const int* in_sizes, int n_in,
                              void* d_out, int out_size) {
    (void)in_sizes; (void)n_in; (void)out_size;
    const float* X1   = (const float*)d_in[0];
    const float* X2   = (const float*)d_in[1];
    const float* XU   = (const float*)d_in[2];
    const float* Acl  = (const float*)d_in[3];
    const float* Aue  = (const float*)d_in[4];
    const float* W1w0 = (const float*)d_in[5];
    const float* W1b0 = (const float*)d_in[6];
    const float* W1w  = (const float*)d_in[7];
    const float* W1b  = (const float*)d_in[8];
    const float* W2w0 = (const float*)d_in[9];
    const float* W2b0 = (const float*)d_in[10];
    const float* W2w  = (const float*)d_in[11];
    const float* W2b  = (const float*)d_in[12];
    const float* W3w0 = (const float*)d_in[13];
    const float* W3b0 = (const float*)d_in[14];
    const float* W3w  = (const float*)d_in[15];
    const float* W3b  = (const float*)d_in[16];
    const float* Qw1  = (const float*)d_in[17];
    const float* Qb1  = (const float*)d_in[18];
    const float* Qw2  = (const float*)d_in[19];
    const float* Qb2  = (const float*)d_in[20];
    float* out = (float*)d_out;

    const int DSMEM = 4 * 10240 + 4 * 10240;  // 81920 B -> 2 CTAs/SM
    cudaFuncSetAttribute(gnn_gemm_kernel, cudaFuncAttributeMaxDynamicSharedMemorySize, DSMEM);

    // layer 0
    h0_kernel<<<32, 256>>>(X1, X2, XU, W1w0, W1b0, W2w0, W2b0, W3w0, W3b0);
    gnn_gemm_kernel<<<256, 256, DSMEM>>>(Acl, Aue);

    // layers 1..2
    for (int l = 1; l <= 2; ++l) {
        h_layer_kernel<<<512, 256>>>(W1w + (l - 1) * 4096, W1b + (l - 1) * 64,
                                     W2w + (l - 1) * 4096, W2b + (l - 1) * 64,
                                     W3w + (l - 1) * 4096, W3b + (l - 1) * 64);
        gnn_gemm_kernel<<<256, 256, DSMEM>>>(Acl, Aue);
    }

    // layer 3: H_cl only + pooling partials, then final MLP
    h_pool_kernel<<<512, 256>>>(W1w + 2 * 4096, W1b + 2 * 64, W2w + 2 * 4096, W2b + 2 * 64);
    final_kernel<<<1, 256>>>(Qw1, Qb1, Qw2, Qb2, out);
}

// round 10
// speedup vs baseline: 1.3867x; 1.0071x over previous
#include <cuda_runtime.h>
#include <cuda_bf16.h>
#include <cstdint>
#include <cstddef>

#define N_NODES 8192
#define DHID 64

// ---------------- scratch (device globals; no allocation allowed) ----------------
__device__ __align__(16) __nv_bfloat16 g_HclT[DHID * N_NODES];  // H_cl^T bf16 [64][8192]
__device__ __align__(16) __nv_bfloat16 g_HueT[DHID * N_NODES];  // H_ue^T bf16 [64][8192]
__device__ __align__(16) float g_Xc1[N_NODES * DHID];
__device__ __align__(16) float g_Xc2[N_NODES * DHID];
__device__ __align__(16) float g_Xue[N_NODES * DHID];
__device__ __align__(16) float g_part[512 * DHID];

__device__ __forceinline__ float relu_(float x) { return fmaxf(x, 0.0f); }

__device__ __forceinline__ uint32_t smem_u32(const void* p) {
    uint32_t a;
    asm("{ .reg .u64 t; cvta.to.shared.u64 t, %1; cvt.u32.u64 %0, t; }" : "=r"(a) : "l"(p));
    return a;
}

__device__ __forceinline__ void ldsm_x4(uint32_t* r, uint32_t addr) {
    asm volatile("ldmatrix.sync.aligned.m8n8.x4.shared.b16 {%0,%1,%2,%3}, [%4];"
                 : "=r"(r[0]), "=r"(r[1]), "=r"(r[2]), "=r"(r[3]) : "r"(addr));
}

__device__ __forceinline__ void mma_bf16(float* c, const uint32_t* a, const uint32_t* b) {
    asm volatile(
        "mma.sync.aligned.m16n8k16.row.col.f32.bf16.bf16.f32 "
        "{%0,%1,%2,%3}, {%4,%5,%6,%7}, {%8,%9}, {%0,%1,%2,%3};"
        : "+f"(c[0]), "+f"(c[1]), "+f"(c[2]), "+f"(c[3])
        : "r"(a[0]), "r"(a[1]), "r"(a[2]), "r"(a[3]), "r"(b[0]), "r"(b[1]));
}

__device__ __forceinline__ uint32_t pack_bf16x2(float2 v) {
    __nv_bfloat162 b = __float22bfloat162_rn(v);
    return *(uint32_t*)&b;
}

#define CP_ASYNC16(smem, gptr) \
    asm volatile("cp.async.cg.shared.global [%0], [%1], 16;" :: "r"(smem), "l"(gptr))
#define CP_COMMIT() asm volatile("cp.async.commit_group;")
#define CP_WAIT2()  asm volatile("cp.async.wait_group 2;")

// ---------------- GEMM body: C[32-row tile, ND] = A(fp32) @ Ht^T (Ht bf16 [n][k]) ----------------
// NT=1: ND=64,  C0 = g_Xc1 (Bt0 = HclT)
// NT=2: ND=128, cols 0-63 -> C0 = g_Xc2 (Bt0 = HueT), cols 64-127 -> C1 = g_Xue (Bt1 = HclT)
template <int NT>
__device__ __forceinline__ void gemm_body(const float* __restrict__ A,
                                          const __nv_bfloat16* __restrict__ Bt0,
                                          const __nv_bfloat16* __restrict__ Bt1,
                                          float* __restrict__ C0, float* __restrict__ C1,
                                          int m0, char* smem) {
    constexpr int ND     = 64 * NT;
    constexpr int KC     = 32;                 // k per chunk
    constexpr int NCH    = N_NODES / KC;       // 256 chunks
    constexpr int STAGES = 4;
    constexpr int ASTR   = 160;                // fp32 A row stride (128B data + 32 pad)
    constexpr int ABUF   = 32 * ASTR;          // 5120 B per stage (32-row M tile)
    constexpr int BSTR   = 80;                 // bf16 B row stride
    constexpr int BBUF   = 128 * BSTR;         // 10240 B per stage (sized for NT=2)
    constexpr int NWID   = ND / 4;             // warp n-width (4 N-warps)
    constexpr int NP     = NT;                 // ldmatrix-x4 per ks per warp

    const int tid  = threadIdx.x;
    const int lane = tid & 31;
    const int wid  = tid >> 5;
    const int wm   = wid & 1;                  // 2 M-warps x 16 rows
    const int wn   = wid >> 1;                 // 4 N-warps x NWID cols
    const int g    = lane >> 2;
    const int t    = lane & 3;

    const uint32_t sbu = smem_u32(smem);
    const uint32_t sA0 = sbu;                  // STAGES stages of A
    const uint32_t sB0 = sbu + STAGES * ABUF;  // STAGES stages of B

    // ---- cp.async slot maps ----
    // A: 32 rows x 8 x 16B slots = 256 slots, 1 per thread
    const int arow = tid >> 3, aseg = tid & 7;
    const float*   gAp   = A + (size_t)(m0 + arow) * N_NODES + aseg * 4;
    const uint32_t aoffS = (uint32_t)(arow * ASTR + aseg * 16);

    // B: ND rows x 4 x 16B slots, NT per thread
    const __nv_bfloat16* gBp[NT];
    uint32_t boffS[NT];
    #pragma unroll
    for (int j = 0; j < NT; ++j) {
        int slot = tid + j * 256;
        int row = slot >> 2, seg = slot & 3;
        const __nv_bfloat16* base = (NT == 2 && row >= 64)
            ? (Bt1 + (size_t)(row - 64) * N_NODES) : (Bt0 + (size_t)row * N_NODES);
        gBp[j]   = base + seg * 8;
        boffS[j] = (uint32_t)(row * BSTR + seg * 16);
    }

    auto ISSUE = [&](int kt) {
        const int s = kt & (STAGES - 1);
        CP_ASYNC16(sA0 + s * ABUF + aoffS, gAp + (size_t)kt * KC);
        const uint32_t sb = sB0 + s * BBUF;
        #pragma unroll
        for (int j = 0; j < NT; ++j)
            CP_ASYNC16(sb + boffS[j], gBp[j] + (size_t)kt * KC);
    };

    // ---- B ldmatrix lane offsets (validated layout, 80B stride) ----
    uint32_t boffL[NP][2];
    #pragma unroll
    for (int np = 0; np < NP; ++np)
        #pragma unroll
        for (int ks = 0; ks < 2; ++ks)
            boffL[np][ks] = (uint32_t)((wn * NWID + np * 16 + (lane >> 4) * 8 + (lane & 7)) * BSTR +
                                       (ks * 16 + ((lane >> 3) & 1) * 8) * 2);

    // ---- A fragment base (fp32 smem, LDS.64 + cvt path) ----
    const int afrag_base = (wm * 16 + g) * ASTR + t * 8;

    float acc[2 * NP][4];
    #pragma unroll
    for (int nt = 0; nt < 2 * NP; ++nt)
        #pragma unroll
        for (int i = 0; i < 4; ++i) acc[nt][i] = 0.0f;

    // ---- prologue: fill STAGES-1 stages ----
    #pragma unroll
    for (int s = 0; s < STAGES - 1; ++s) { ISSUE(s); CP_COMMIT(); }

    for (int kt = 0; kt < NCH; ++kt) {
        const int st = kt & (STAGES - 1);
        CP_WAIT2();
        __syncthreads();

        if (kt + STAGES - 1 < NCH) ISSUE(kt + STAGES - 1);
        CP_COMMIT();

        const char*    Ab = smem + st * ABUF + afrag_base;
        const uint32_t Bb = sB0 + st * BBUF;

        #pragma unroll
        for (int ks = 0; ks < 2; ++ks) {
            uint32_t af[4], bf[2 * NP][2];
            {
                const char* p = Ab + ks * 64;
                af[0] = pack_bf16x2(*(const float2*)(p));
                af[1] = pack_bf16x2(*(const float2*)(p + 8 * ASTR));
                af[2] = pack_bf16x2(*(const float2*)(p + 32));
                af[3] = pack_bf16x2(*(const float2*)(p + 8 * ASTR + 32));
            }
            #pragma unroll
            for (int np = 0; np < NP; ++np) {
                uint32_t tt[4];
                ldsm_x4(tt, Bb + boffL[np][ks]);
                bf[np * 2][0] = tt[0]; bf[np * 2][1] = tt[1];
                bf[np * 2 + 1][0] = tt[2]; bf[np * 2 + 1][1] = tt[3];
            }
            #pragma unroll
            for (int nt = 0; nt < 2 * NP; ++nt)
                mma_bf16(acc[nt], af, bf[nt]);
        }
    }

    // ---- epilogue ----
    const int tig = lane & 3;
    {
        int row = m0 + wm * 16 + g;
        #pragma unroll
        for (int nt = 0; nt < 2 * NP; ++nt) {
            int col = wn * NWID + nt * 8 + tig * 2;
            float* Cg = C0;
            int cc = col;
            if (NT == 2 && col >= 64) { Cg = C1; cc = col - 64; }
            *(float2*)(Cg + (size_t)row * 64 + cc)       = make_float2(acc[nt][0], acc[nt][1]);
            *(float2*)(Cg + (size_t)(row + 8) * 64 + cc) = make_float2(acc[nt][2], acc[nt][3]);
        }
    }
}

__global__ void __launch_bounds__(256, 3)
gnn_gemm_kernel(const float* __restrict__ Acl, const float* __restrict__ Aue) {
    extern __shared__ __align__(128) char smem[];   // 4*5120 + 4*10240 = 61440 B
    const int b = blockIdx.x;
    const int tile = b >> 1;
    if ((b & 1) == 0) gemm_body<1>(Acl, g_HclT, nullptr, g_Xc1, nullptr, tile * 32, smem);
    else              gemm_body<2>(Aue, g_HueT, g_HclT, g_Xc2, g_Xue, tile * 32, smem);
}

// ---------------- layer 0 H (in_dim = 2), writes H^T bf16 ----------------
__global__ void h0_kernel(const float* __restrict__ X1, const float* __restrict__ X2,
                          const float* __restrict__ XU,
                          const float* __restrict__ w1, const float* __restrict__ b1,
                          const float* __restrict__ w2, const float* __restrict__ b2,
                          const float* __restrict__ w3, const float* __restrict__ b3) {
    const int r = blockIdx.x * 256 + threadIdx.x;
    const float2 x1 = *(const float2*)(X1 + r * 2);
    const float2 x2 = *(const float2*)(X2 + r * 2);
    const float2 xu = *(const float2*)(XU + r * 2);
    #pragma unroll 8
    for (int c = 0; c < 64; ++c) {
        float h1 = relu_(fmaf(x1.x, __ldg(w1 + c), fmaf(x1.y, __ldg(w1 + 64 + c), __ldg(b1 + c))));
        float h2 = relu_(fmaf(x2.x, __ldg(w2 + c), fmaf(x2.y, __ldg(w2 + 64 + c), __ldg(b2 + c))));
        float h3 = relu_(fmaf(xu.x, __ldg(w3 + c), fmaf(xu.y, __ldg(w3 + 64 + c), __ldg(b3 + c))));
        g_HclT[c * N_NODES + r] = __float2bfloat16(h1 + h2);
        g_HueT[c * N_NODES + r] = __float2bfloat16(h3);
    }
}

// ---------------- layers 1..2 H (in_dim = 64), writes H^T bf16 ----------------
__global__ void __launch_bounds__(256) h_layer_kernel(const float* __restrict__ w1,
                                                      const float* __restrict__ b1,
                                                      const float* __restrict__ w2,
                                                      const float* __restrict__ b2,
                                                      const float* __restrict__ w3,
                                                      const float* __restrict__ b3) {
    __shared__ float xs1[16][64], xs2[16][64], xs3[16][64];
    __shared__ __align__(16) __nv_bfloat16 hs_cl[64][16];
    __shared__ __align__(16) __nv_bfloat16 hs_ue[64][16];
    const int tid = threadIdx.x;
    const int r0  = blockIdx.x * 16;
    #pragma unroll
    for (int i = 0; i < 4; ++i) {
        int idx = tid + i * 256;
        int r = idx >> 6, k = idx & 63;
        xs1[r][k] = g_Xc1[(size_t)(r0 + r) * 64 + k];
        xs2[r][k] = g_Xc2[(size_t)(r0 + r) * 64 + k];
        xs3[r][k] = g_Xue[(size_t)(r0 + r) * 64 + k];
    }
    __syncthreads();
    const int c  = tid & 63;
    const int rg = tid >> 6;
    float a1[4] = {0, 0, 0, 0}, a2[4] = {0, 0, 0, 0}, a3[4] = {0, 0, 0, 0};
    #pragma unroll 8
    for (int k = 0; k < 64; ++k) {
        float w1k = w1[k * 64 + c], w2k = w2[k * 64 + c], w3k = w3[k * 64 + c];
        #pragma unroll
        for (int i = 0; i < 4; ++i) {
            int r = rg + i * 4;
            a1[i] = fmaf(xs1[r][k], w1k, a1[i]);
            a2[i] = fmaf(xs2[r][k], w2k, a2[i]);
            a3[i] = fmaf(xs3[r][k], w3k, a3[i]);
        }
    }
    const float bb1 = b1[c], bb2 = b2[c], bb3 = b3[c];
    #pragma unroll
    for (int i = 0; i < 4; ++i) {
        int r = rg + i * 4;
        hs_cl[c][r] = __float2bfloat16(relu_(a1[i] + bb1) + relu_(a2[i] + bb2));
        hs_ue[c][r] = __float2bfloat16(relu_(a3[i] + bb3));
    }
    __syncthreads();
    if (tid < 128) {
        int cc = tid >> 1, hf = tid & 1;
        *(uint4*)(g_HclT + cc * N_NODES + r0 + hf * 8) = *(const uint4*)(&hs_cl[cc][hf * 8]);
    } else {
        int tt = tid - 128;
        int cc = tt >> 1, hf = tt & 1;
        *(uint4*)(g_HueT + cc * N_NODES + r0 + hf * 8) = *(const uint4*)(&hs_ue[cc][hf * 8]);
    }
}

// ---------------- layer 3: H_cl + column-sum partials (X updates are dead) ----------------
__global__ void __launch_bounds__(256) h_pool_kernel(const float* __restrict__ w1,
                                                     const float* __restrict__ b1,
                                                     const float* __restrict__ w2,
                                                     const float* __restrict__ b2) {
    __shared__ float xs1[16][64], xs2[16][64];
    __shared__ float red[4][64];
    const int tid = threadIdx.x;
    const int r0  = blockIdx.x * 16;
    #pragma unroll
    for (int i = 0; i < 4; ++i) {
        int idx = tid + i * 256;
        int r = idx >> 6, k = idx & 63;
        xs1[r][k] = g_Xc1[(size_t)(r0 + r) * 64 + k];
        xs2[r][k] = g_Xc2[(size_t)(r0 + r) * 64 + k];
    }
    __syncthreads();
    const int c  = tid & 63;
    const int rg = tid >> 6;
    float a1[4] = {0, 0, 0, 0}, a2[4] = {0, 0, 0, 0};
    #pragma unroll 8
    for (int k = 0; k < 64; ++k) {
        float w1k = w1[k * 64 + c], w2k = w2[k * 64 + c];
        #pragma unroll
        for (int i = 0; i < 4; ++i) {
            int r = rg + i * 4;
            a1[i] = fmaf(xs1[r][k], w1k, a1[i]);
            a2[i] = fmaf(xs2[r][k], w2k, a2[i]);
        }
    }
    const float bb1 = b1[c], bb2 = b2[c];
    float s = 0.0f;
    #pragma unroll
    for (int i = 0; i < 4; ++i) s += relu_(a1[i] + bb1) + relu_(a2[i] + bb2);
    red[rg][c] = s;
    __syncthreads();
    if (tid < 64)
        g_part[blockIdx.x * 64 + tid] = red[0][tid] + red[1][tid] + red[2][tid] + red[3][tid];
}

// ---------------- final: reduce partials + 2-layer MLP -> out[0] ----------------
__global__ void final_kernel(const float* __restrict__ Qw1, const float* __restrict__ Qb1,
                             const float* __restrict__ Qw2, const float* __restrict__ Qb2,
                             float* __restrict__ out) {
    __shared__ float red[4][64];
    __shared__ float pooled[64];
    __shared__ float z[64];
    int tid = threadIdx.x;
    int c = tid & 63, g = tid >> 6;
    float s = 0.0f;
    for (int p = g; p < 512; p += 4) s += g_part[p * 64 + c];
    red[g][c] = s;
    __syncthreads();
    if (tid < 64) pooled[tid] = red[0][tid] + red[1][tid] + red[2][tid] + red[3][tid];
    __syncthreads();
    if (tid < 64) {
        float a = Qb1[tid];
        #pragma unroll 8
        for (int i = 0; i < 64; ++i) a = fmaf(pooled[i], Qw1[i * 64 + tid], a);
        z[tid] = relu_(a);
    }
    __syncthreads();
    if (tid == 0) {
        float s2 = Qb2[0];
        for (int j = 0; j < 64; ++j) s2 = fmaf(z[j], Qw2[j], s2);
        out[0] = s2;
    }
}

// ---------------- launch ----------------
extern "C" void kernel_launch(void* const* d_in, const int* in_sizes, int n_in,
                              void* d_out, int out_size) {
    (void)in_sizes; (void)n_in; (void)out_size;
    const float* X1   = (const float*)d_in[0];
    const float* X2   = (const float*)d_in[1];
    const float* XU   = (const float*)d_in[2];
    const float* Acl  = (const float*)d_in[3];
    const float* Aue  = (const float*)d_in[4];
    const float* W1w0 = (const float*)d_in[5];
    const float* W1b0 = (const float*)d_in[6];
    const float* W1w  = (const float*)d_in[7];
    const float* W1b  = (const float*)d_in[8];
    const float* W2w0 = (const float*)d_in[9];
    const float* W2b0 = (const float*)d_in[10];
    const float* W2w  = (const float*)d_in[11];
    const float* W2b  = (const float*)d_in[12];
    const float* W3w0 = (const float*)d_in[13];
    const float* W3b0 = (const float*)d_in[14];
    const float* W3w  = (const float*)d_in[15];
    const float* W3b  = (const float*)d_in[16];
    const float* Qw1  = (const float*)d_in[17];
    const float* Qb1  = (const float*)d_in[18];
    const float* Qw2  = (const float*)d_in[19];
    const float* Qb2  = (const float*)d_in[20];
    float* out = (float*)d_out;

    const int DSMEM = 4 * 5120 + 4 * 10240;  // 61440 B -> 3 CTAs/SM
    cudaFuncSetAttribute(gnn_gemm_kernel, cudaFuncAttributeMaxDynamicSharedMemorySize, DSMEM);

    // layer 0
    h0_kernel<<<32, 256>>>(X1, X2, XU, W1w0, W1b0, W2w0, W2b0, W3w0, W3b0);
    gnn_gemm_kernel<<<512, 256, DSMEM>>>(Acl, Aue);

    // layers 1..2
    for (int l = 1; l <= 2; ++l) {
        h_layer_kernel<<<512, 256>>>(W1w + (l - 1) * 4096, W1b + (l - 1) * 64,
                                     W2w + (l - 1) * 4096, W2b + (l - 1) * 64,
                                     W3w + (l - 1) * 4096, W3b + (l - 1) * 64);
        gnn_gemm_kernel<<<512, 256, DSMEM>>>(Acl, Aue);
    }

    // layer 3: H_cl only + pooling partials, then final MLP
    h_pool_kernel<<<512, 256>>>(W1w + 2 * 4096, W1b + 2 * 64, W2w + 2 * 4096, W2b + 2 * 64);
    final_kernel<<<1, 256>>>(Qw1, Qb1, Qw2, Qb2, out);
}